// round 13
// baseline (speedup 1.0000x reference)
#include <cuda_runtime.h>
#include <cuda_bf16.h>
#include <math.h>
#include <stdint.h>

// Problem constants
#define Bsz   16
#define Cc    256
#define Nn    4096     // H*W = 64*64
#define NHEAD 4
#define HIDc  512
#define MQ    128      // NHEAD*32
#define MU    1024     // 2*HID
#define EPSf  1e-5f
#define SCALEq 0.4204482076268573f   // 32^(-0.25)

// ---------------- single byte arena (device global; allocation-free) -------
#define ALGN(x) (((x) + 255) & ~(size_t)255)
#define BY_XN    ((size_t)0)                                  // bf16 [16,256,4096]
#define SZ_XN_B  ((size_t)Bsz * Cc * Nn * 2)
#define BY_Q     ALGN(BY_XN + SZ_XN_B)                        // bf16 [16,128,4096] x3 contiguous
#define SZ_QKV_B ((size_t)Bsz * MQ * Nn * 2)
#define BY_K     (BY_Q + SZ_QKV_B)                            // holds exp(k~)
#define BY_V     (BY_K + SZ_QKV_B)
#define BY_X1    ALGN(BY_V + SZ_QKV_B)                        // f32 [16,256,4096]
#define SZ_X1_B  ((size_t)Bsz * Cc * Nn * 4)
#define BY_U     ALGN(BY_X1 + SZ_X1_B)                        // bf16 [16,1024,4096]
#define SZ_U_B   ((size_t)Bsz * MU * Nn * 2)
#define BY_GATE  ALGN(BY_U + SZ_U_B)                          // bf16 [16,512,4096]
#define SZ_GATE_B ((size_t)Bsz * HIDc * Nn * 2)
#define BY_CTX   ALGN(BY_GATE + SZ_GATE_B)                    // f32 [64,4,1024] partials
#define SZ_CTX_B ((size_t)Bsz * NHEAD * 4 * 1024 * 4)
#define BY_Z     ALGN(BY_CTX + SZ_CTX_B)                      // f32 [64,4,32] partials
#define SZ_Z_B   ((size_t)Bsz * NHEAD * 4 * 32 * 4)
#define BY_WQKV  ALGN(BY_Z + SZ_Z_B)                          // bf16 [384,256]
#define BY_BQKV  ALGN(BY_WQKV + (size_t)384 * 256 * 2)        // f32 [384]
#define BY_WC    ALGN(BY_BQKV + 2048)                         // bf16 [16,256,128]
#define BY_PW1   ALGN(BY_WC + (size_t)Bsz * 256 * 128 * 2)    // bf16 [1024,256]
#define BY_PW2   ALGN(BY_PW1 + (size_t)1024 * 256 * 2)        // bf16 [256,512]
#define ARENA_BYTES (BY_PW2 + (size_t)256 * 512 * 2)

__device__ __align__(256) unsigned char g_arena[ARENA_BYTES];

// ---------------- cp.async helpers ----------------
__device__ __forceinline__ void cp_async16(void* dst, const void* src) {
    uint32_t d = (uint32_t)__cvta_generic_to_shared(dst);
    asm volatile("cp.async.ca.shared.global [%0], [%1], 16;" :: "r"(d), "l"(src));
}
__device__ __forceinline__ void cp_commit() { asm volatile("cp.async.commit_group;"); }
template<int N> __device__ __forceinline__ void cp_wait() {
    asm volatile("cp.async.wait_group %0;" :: "n"(N));
}

// ---------------- ldmatrix + bf16 MMA ----------------
__device__ __forceinline__ void ldsm_x4(uint32_t* r, uint32_t addr) {
    asm volatile("ldmatrix.sync.aligned.m8n8.x4.shared.b16 {%0,%1,%2,%3}, [%4];"
        : "=r"(r[0]), "=r"(r[1]), "=r"(r[2]), "=r"(r[3]) : "r"(addr));
}
__device__ __forceinline__ void ldsm_x4t(uint32_t* r, uint32_t addr) {
    asm volatile("ldmatrix.sync.aligned.m8n8.x4.trans.shared.b16 {%0,%1,%2,%3}, [%4];"
        : "=r"(r[0]), "=r"(r[1]), "=r"(r[2]), "=r"(r[3]) : "r"(addr));
}
__device__ __forceinline__ void mma_bf16(float* c, const uint32_t* a, uint32_t b0, uint32_t b1) {
    asm volatile("mma.sync.aligned.m16n8k16.row.col.f32.bf16.bf16.f32 "
        "{%0,%1,%2,%3}, {%4,%5,%6,%7}, {%8,%9}, {%0,%1,%2,%3};"
        : "+f"(c[0]), "+f"(c[1]), "+f"(c[2]), "+f"(c[3])
        : "r"(a[0]), "r"(a[1]), "r"(a[2]), "r"(a[3]), "r"(b0), "r"(b1));
}

// ---------------- weight conversion (fp32 -> bf16, packed qkv) -------------
__global__ void conv_weights(const float* __restrict__ wq, const float* __restrict__ wk,
                             const float* __restrict__ wv, const float* __restrict__ bq,
                             const float* __restrict__ bk, const float* __restrict__ bv,
                             const float* __restrict__ pw1, const float* __restrict__ pw2,
                             __nv_bfloat16* __restrict__ wqkv, float* __restrict__ bqkv,
                             __nv_bfloat16* __restrict__ pw1b, __nv_bfloat16* __restrict__ pw2b)
{
    int i = blockIdx.x * 256 + threadIdx.x;           // 0 .. 491519
    if (i < 32768)        wqkv[i] = __float2bfloat16(wq[i]);
    else if (i < 65536)   wqkv[i] = __float2bfloat16(wk[i - 32768]);
    else if (i < 98304)   wqkv[i] = __float2bfloat16(wv[i - 65536]);
    else if (i < 360448)  pw1b[i - 98304]  = __float2bfloat16(pw1[i - 98304]);
    else                  pw2b[i - 360448] = __float2bfloat16(pw2[i - 360448]);
    if (i < 128)              bqkv[i] = bq[i];
    else if (i < 256)         bqkv[i] = bk[i - 128];
    else if (i < 384)         bqkv[i] = bv[i - 256];
}

// ------- LayerNorm over channels; 2 pixels per thread (float2/bf162) -------
__global__ void ln_channels(const float* __restrict__ x,
                            const float* __restrict__ w,
                            const float* __restrict__ bc,
                            __nv_bfloat16* __restrict__ y)
{
    int p = (blockIdx.x * 256 + threadIdx.x) * 2;     // even pixel index
    int b = blockIdx.y;
    const float2* xb = (const float2*)(x + (size_t)b * Cc * Nn) + (p >> 1);
    float2 s = make_float2(0.f, 0.f), s2 = make_float2(0.f, 0.f);
    #pragma unroll 8
    for (int c = 0; c < Cc; ++c) {
        float2 v = xb[(size_t)c * (Nn >> 1)];
        s.x += v.x; s.y += v.y;
        s2.x = fmaf(v.x, v.x, s2.x);
        s2.y = fmaf(v.y, v.y, s2.y);
    }
    float mx = s.x * (1.f / Cc), my = s.y * (1.f / Cc);
    float rx = rsqrtf(s2.x * (1.f / Cc) - mx * mx + EPSf);
    float ry = rsqrtf(s2.y * (1.f / Cc) - my * my + EPSf);
    __nv_bfloat162* yb = (__nv_bfloat162*)(y + (size_t)b * Cc * Nn + p);
    #pragma unroll 8
    for (int c = 0; c < Cc; ++c) {
        float2 v = xb[(size_t)c * (Nn >> 1)];
        float wv = w[c], bv = bc[c];
        yb[(size_t)c * (Nn >> 1)] = __floats2bfloat162_rn(
            (v.x - mx) * rx * wv + bv, (v.y - my) * ry * wv + bv);
    }
}

// ---------------- bf16 tensor-core GEMM, 4-stage BK=16 pipeline ------------
// OM: 0 = f32 out (+bias/+res), 1 = bf16 out, 2 = fused qkv head-norm epilogue
#define SA_STR 24              // 16 + 8 pad (bf16 units)
#define SB_STR 136             // 128 + 8 pad
#define SA_BUF (128 * SA_STR)
#define SB_BUF (16 * SB_STR)
#define NSTG 4

template<bool BIAS, bool RES, int OM>
__global__ void __launch_bounds__(256, 2)
gemm_bf16(const __nv_bfloat16* __restrict__ W,     // [(b),Mtot,K] row-major
          const __nv_bfloat16* __restrict__ X,     // [B,K,N]
          const float* __restrict__ bias,          // [Mtot]
          const float* __restrict__ res,           // same layout as Y (f32)
          void* __restrict__ Yv,
          int K, size_t wstride, size_t strideB, size_t strideY,
          const float* __restrict__ nqw, const float* __restrict__ nqb,
          const float* __restrict__ nkw, const float* __restrict__ nkb,
          const float* __restrict__ nvw, const float* __restrict__ nvb)
{
    __shared__ __nv_bfloat16 sA[NSTG * SA_BUF];
    __shared__ __nv_bfloat16 sB[NSTG * SB_BUF];

    const int b  = blockIdx.z;
    const int m0 = blockIdx.y * 128;
    const int n0 = blockIdx.x * 128;
    const int tid  = threadIdx.x;
    const int lane = tid & 31, wid = tid >> 5;
    const int g = lane >> 2, t = lane & 3;
    const int mw = (wid & 3) * 32;
    const int nw = (wid >> 2) * 64;

    const __nv_bfloat16* Wp = W + (size_t)b * wstride + (size_t)m0 * K;
    const __nv_bfloat16* Xp = X + (size_t)b * K * Nn + n0;

    float acc[2][8][4];
    #pragma unroll
    for (int r = 0; r < 2; ++r)
        #pragma unroll
        for (int f = 0; f < 8; ++f)
            #pragma unroll
            for (int i = 0; i < 4; ++i) acc[r][f][i] = 0.f;

    const int ra = tid >> 1, ca = (tid & 1) * 8;
    const int rb = tid >> 4, cb = (tid & 15) * 8;
    auto issue = [&](int buf, int k0) {
        cp_async16(sA + buf * SA_BUF + ra * SA_STR + ca, Wp + (size_t)ra * K + k0 + ca);
        cp_async16(sB + buf * SB_BUF + rb * SB_STR + cb, Xp + (size_t)(k0 + rb) * Nn + cb);
    };

    const uint32_t sA32 = (uint32_t)__cvta_generic_to_shared(sA);
    const uint32_t sB32 = (uint32_t)__cvta_generic_to_shared(sB);
    const int aRow = mw + (lane & 15);
    const int aKof = (lane >> 4) * 8;
    const int bRow = lane & 15;
    const int bNof = nw + (lane >> 4) * 8;

    const int KT = K >> 4;
    #pragma unroll
    for (int s = 0; s < NSTG - 1; ++s) { issue(s, s << 4); cp_commit(); }

    for (int kt = 0; kt < KT; ++kt) {
        cp_wait<NSTG - 2>();
        __syncthreads();

        int buf = kt & (NSTG - 1);
        uint32_t abase = sA32 + (buf * SA_BUF) * 2;
        uint32_t bbase = sB32 + (buf * SB_BUF) * 2;
        uint32_t af[2][4];
        #pragma unroll
        for (int r = 0; r < 2; ++r)
            ldsm_x4(af[r], abase + ((aRow + r * 16) * SA_STR + aKof) * 2);
        uint32_t bfr[4][4];
        #pragma unroll
        for (int fc = 0; fc < 4; ++fc)
            ldsm_x4t(bfr[fc], bbase + (bRow * SB_STR + bNof + fc * 16) * 2);
        #pragma unroll
        for (int r = 0; r < 2; ++r)
            #pragma unroll
            for (int fc = 0; fc < 4; ++fc) {
                mma_bf16(acc[r][2 * fc],     af[r], bfr[fc][0], bfr[fc][1]);
                mma_bf16(acc[r][2 * fc + 1], af[r], bfr[fc][2], bfr[fc][3]);
            }

        if (kt + NSTG - 1 < KT) issue((kt + NSTG - 1) & (NSTG - 1), (kt + NSTG - 1) << 4);
        cp_commit();   // always commit (keeps wait_group bookkeeping exact)
    }

    if constexpr (OM == 2) {
        // fused per-head LN (+softmax over d for q; exp for k) epilogue
        const int mode = blockIdx.y;     // 0=q, 1=k (stores exp), 2=v
        const float* hw = mode == 0 ? nqw : (mode == 1 ? nkw : nvw);
        const float* hb = mode == 0 ? nqb : (mode == 1 ? nkb : nvb);
        float wd[4], bd[4], bi[4];
        #pragma unroll
        for (int r4 = 0; r4 < 4; ++r4) {
            int d = r4 * 8 + g;
            wd[r4] = hw[d]; bd[r4] = hb[d];
            bi[r4] = bias[m0 + mw + d];
        }
        __nv_bfloat16* Y = (__nv_bfloat16*)Yv;
        const size_t ybase = (size_t)b * strideB + (size_t)blockIdx.y * strideY + n0;
        #pragma unroll
        for (int f = 0; f < 8; ++f) {
            float ov[2][4];
            #pragma unroll
            for (int j = 0; j < 2; ++j) {
                float v0 = acc[0][f][j]     + bi[0];
                float v1 = acc[0][f][j + 2] + bi[1];
                float v2 = acc[1][f][j]     + bi[2];
                float v3 = acc[1][f][j + 2] + bi[3];
                float s  = v0 + v1 + v2 + v3;
                float sq = v0*v0 + v1*v1 + v2*v2 + v3*v3;
                #pragma unroll
                for (int m = 4; m <= 16; m <<= 1) {
                    s  += __shfl_xor_sync(0xffffffffu, s,  m);
                    sq += __shfl_xor_sync(0xffffffffu, sq, m);
                }
                float mean = s * (1.f / 32.f);
                float var  = sq * (1.f / 32.f) - mean * mean;
                float rstd = rsqrtf(var + EPSf);
                float n0v = (v0 - mean) * rstd * wd[0] + bd[0];
                float n1v = (v1 - mean) * rstd * wd[1] + bd[1];
                float n2v = (v2 - mean) * rstd * wd[2] + bd[2];
                float n3v = (v3 - mean) * rstd * wd[3] + bd[3];
                if (mode < 2) { n0v *= SCALEq; n1v *= SCALEq; n2v *= SCALEq; n3v *= SCALEq; }
                if (mode == 0) {
                    float mx = fmaxf(fmaxf(n0v, n1v), fmaxf(n2v, n3v));
                    #pragma unroll
                    for (int m = 4; m <= 16; m <<= 1)
                        mx = fmaxf(mx, __shfl_xor_sync(0xffffffffu, mx, m));
                    n0v = __expf(n0v - mx); n1v = __expf(n1v - mx);
                    n2v = __expf(n2v - mx); n3v = __expf(n3v - mx);
                    float se = n0v + n1v + n2v + n3v;
                    #pragma unroll
                    for (int m = 4; m <= 16; m <<= 1)
                        se += __shfl_xor_sync(0xffffffffu, se, m);
                    float inv = 1.f / se;
                    n0v *= inv; n1v *= inv; n2v *= inv; n3v *= inv;
                } else if (mode == 1) {
                    // k is only ever consumed as exp(k~): store exp directly
                    n0v = __expf(n0v); n1v = __expf(n1v);
                    n2v = __expf(n2v); n3v = __expf(n3v);
                }
                ov[j][0] = n0v; ov[j][1] = n1v; ov[j][2] = n2v; ov[j][3] = n3v;
            }
            int col = nw + f * 8 + 2 * t;
            #pragma unroll
            for (int r4 = 0; r4 < 4; ++r4) {
                size_t idx = ybase + (size_t)(mw + r4 * 8 + g) * Nn + col;
                *(__nv_bfloat162*)(Y + idx) = __floats2bfloat162_rn(ov[0][r4], ov[1][r4]);
            }
        }
    } else {
        const size_t ybase = (size_t)b * strideB + (size_t)blockIdx.y * strideY + n0;
        #pragma unroll
        for (int r = 0; r < 2; ++r) {
            int rl0 = mw + r * 16 + g;
            int rl1 = rl0 + 8;
            float b0v = BIAS ? bias[m0 + rl0] : 0.f;
            float b1v = BIAS ? bias[m0 + rl1] : 0.f;
            #pragma unroll
            for (int f = 0; f < 8; ++f) {
                int col = nw + f * 8 + 2 * t;
                size_t i0 = ybase + (size_t)rl0 * Nn + col;
                size_t i1 = ybase + (size_t)rl1 * Nn + col;
                float2 v0 = make_float2(acc[r][f][0] + b0v, acc[r][f][1] + b0v);
                float2 v1 = make_float2(acc[r][f][2] + b1v, acc[r][f][3] + b1v);
                if (RES) {
                    float2 r0 = *(const float2*)(res + i0);
                    float2 r1 = *(const float2*)(res + i1);
                    v0.x += r0.x; v0.y += r0.y;
                    v1.x += r1.x; v1.y += r1.y;
                }
                if constexpr (OM == 1) {
                    __nv_bfloat16* Y = (__nv_bfloat16*)Yv;
                    *(__nv_bfloat162*)(Y + i0) = __floats2bfloat162_rn(v0.x, v0.y);
                    *(__nv_bfloat162*)(Y + i1) = __floats2bfloat162_rn(v1.x, v1.y);
                } else {
                    float* Y = (float*)Yv;
                    *(float2*)(Y + i0) = v0;
                    *(float2*)(Y + i1) = v1;
                }
            }
        }
    }
}

// ------- wo GEMM with fused channel-LN: 256x64 tile, 8 m-warps -------------
#define WA_STR 24
#define WA_BUF (256 * WA_STR)
#define WB_STR 72
#define WB_BUF (16 * WB_STR)

__global__ void __launch_bounds__(256, 2)
gemm_wo_ln(const __nv_bfloat16* __restrict__ Wc,   // [b][256][128]
           const __nv_bfloat16* __restrict__ q,    // [b][128][4096]
           const float* __restrict__ bo,
           const float* __restrict__ x,            // [b][256][4096] f32
           const float* __restrict__ ln2w, const float* __restrict__ ln2b,
           float* __restrict__ x1,                 // f32 out
           __nv_bfloat16* __restrict__ xn)         // bf16 LN out
{
    __shared__ __nv_bfloat16 sA[2 * WA_BUF];
    __shared__ __nv_bfloat16 sB[2 * WB_BUF];
    __shared__ float redS[8][64];
    __shared__ float redQ[8][64];
    __shared__ float smean[64], srstd[64];

    const int b  = blockIdx.y;
    const int n0 = blockIdx.x * 64;
    const int tid  = threadIdx.x;
    const int lane = tid & 31, wid = tid >> 5;
    const int g = lane >> 2, t = lane & 3;
    const int mw = wid * 32;

    const __nv_bfloat16* Wp = Wc + (size_t)b * 32768;   // K = 128
    const __nv_bfloat16* Xp = q + (size_t)b * 128 * Nn + n0;

    float acc[2][8][4];
    #pragma unroll
    for (int r = 0; r < 2; ++r)
        #pragma unroll
        for (int f = 0; f < 8; ++f)
            #pragma unroll
            for (int i = 0; i < 4; ++i) acc[r][f][i] = 0.f;

    const int rb = tid >> 3, cb = (tid & 7) * 8;
    auto issue = [&](int buf, int k0) {
        #pragma unroll
        for (int i = 0; i < 2; ++i) {
            int idx = tid + i * 256;
            cp_async16(sA + buf * WA_BUF + (idx >> 1) * WA_STR + (idx & 1) * 8,
                       Wp + (size_t)(idx >> 1) * 128 + k0 + (idx & 1) * 8);
        }
        if (tid < 128)
            cp_async16(sB + buf * WB_BUF + rb * WB_STR + cb,
                       Xp + (size_t)(k0 + rb) * Nn + cb);
    };

    const uint32_t sA32 = (uint32_t)__cvta_generic_to_shared(sA);
    const uint32_t sB32 = (uint32_t)__cvta_generic_to_shared(sB);
    const int aRow = mw + (lane & 15);
    const int aKof = (lane >> 4) * 8;
    const int bRow = lane & 15;
    const int bNof = (lane >> 4) * 8;

    issue(0, 0); cp_commit();
    for (int kt = 0; kt < 8; ++kt) {
        if (kt + 1 < 8) { issue((kt + 1) & 1, (kt + 1) << 4); cp_commit(); cp_wait<1>(); }
        else            { cp_wait<0>(); }
        __syncthreads();
        uint32_t abase = sA32 + ((kt & 1) * WA_BUF) * 2;
        uint32_t bbase = sB32 + ((kt & 1) * WB_BUF) * 2;
        uint32_t af[2][4];
        #pragma unroll
        for (int r = 0; r < 2; ++r)
            ldsm_x4(af[r], abase + ((aRow + r * 16) * WA_STR + aKof) * 2);
        uint32_t bfr[4][4];
        #pragma unroll
        for (int fc = 0; fc < 4; ++fc)
            ldsm_x4t(bfr[fc], bbase + (bRow * WB_STR + bNof + fc * 16) * 2);
        #pragma unroll
        for (int r = 0; r < 2; ++r)
            #pragma unroll
            for (int fc = 0; fc < 4; ++fc) {
                mma_bf16(acc[r][2 * fc],     af[r], bfr[fc][0], bfr[fc][1]);
                mma_bf16(acc[r][2 * fc + 1], af[r], bfr[fc][2], bfr[fc][3]);
            }
        __syncthreads();
    }

    float bi[4], lw[4], lb[4];
    #pragma unroll
    for (int r4 = 0; r4 < 4; ++r4) {
        int m = mw + r4 * 8 + g;
        bi[r4] = bo[m]; lw[r4] = ln2w[m]; lb[r4] = ln2b[m];
    }
    const size_t base = ((size_t)b * Cc) * Nn + n0;
    float csum[8][2], csq[8][2];
    #pragma unroll
    for (int f = 0; f < 8; ++f) {
        int col = f * 8 + 2 * t;
        #pragma unroll
        for (int r = 0; r < 2; ++r) {
            int m0r = mw + r * 16 + g;
            float2 r0 = *(const float2*)(x + base + (size_t)m0r * Nn + col);
            float2 r1 = *(const float2*)(x + base + (size_t)(m0r + 8) * Nn + col);
            acc[r][f][0] += bi[r * 2] + r0.x;
            acc[r][f][1] += bi[r * 2] + r0.y;
            acc[r][f][2] += bi[r * 2 + 1] + r1.x;
            acc[r][f][3] += bi[r * 2 + 1] + r1.y;
        }
        #pragma unroll
        for (int j = 0; j < 2; ++j) {
            float v0 = acc[0][f][j], v1 = acc[0][f][j + 2];
            float v2 = acc[1][f][j], v3 = acc[1][f][j + 2];
            float s  = v0 + v1 + v2 + v3;
            float sq = v0*v0 + v1*v1 + v2*v2 + v3*v3;
            #pragma unroll
            for (int m = 4; m <= 16; m <<= 1) {
                s  += __shfl_xor_sync(0xffffffffu, s,  m);
                sq += __shfl_xor_sync(0xffffffffu, sq, m);
            }
            csum[f][j] = s; csq[f][j] = sq;
        }
    }
    __syncthreads();
    if (g == 0) {
        #pragma unroll
        for (int f = 0; f < 8; ++f) {
            #pragma unroll
            for (int j = 0; j < 2; ++j) {
                redS[wid][f * 8 + 2 * t + j] = csum[f][j];
                redQ[wid][f * 8 + 2 * t + j] = csq[f][j];
            }
        }
    }
    __syncthreads();
    if (tid < 64) {
        float s = 0.f, sq = 0.f;
        #pragma unroll
        for (int w = 0; w < 8; ++w) { s += redS[w][tid]; sq += redQ[w][tid]; }
        float mean = s * (1.f / 256.f);
        float var  = sq * (1.f / 256.f) - mean * mean;
        smean[tid] = mean;
        srstd[tid] = rsqrtf(var + EPSf);
    }
    __syncthreads();
    #pragma unroll
    for (int f = 0; f < 8; ++f) {
        int col = f * 8 + 2 * t;
        float m0c = smean[col], m1c = smean[col + 1];
        float s0c = srstd[col], s1c = srstd[col + 1];
        #pragma unroll
        for (int r = 0; r < 2; ++r) {
            int m0r = mw + r * 16 + g;
            size_t i0 = base + (size_t)m0r * Nn + col;
            size_t i1 = base + (size_t)(m0r + 8) * Nn + col;
            float v0 = acc[r][f][0], v1 = acc[r][f][1];
            float v2 = acc[r][f][2], v3 = acc[r][f][3];
            *(float2*)(x1 + i0) = make_float2(v0, v1);
            *(float2*)(x1 + i1) = make_float2(v2, v3);
            float n0v = (v0 - m0c) * s0c * lw[r * 2]     + lb[r * 2];
            float n1v = (v1 - m1c) * s1c * lw[r * 2]     + lb[r * 2];
            float n2v = (v2 - m0c) * s0c * lw[r * 2 + 1] + lb[r * 2 + 1];
            float n3v = (v3 - m1c) * s1c * lw[r * 2 + 1] + lb[r * 2 + 1];
            *(__nv_bfloat162*)(xn + i0) = __floats2bfloat162_rn(n0v, n1v);
            *(__nv_bfloat162*)(xn + i1) = __floats2bfloat162_rn(n2v, n3v);
        }
    }
}

// ---- ctx via tensor cores: ctx_part[bh][ch] = expK_chunk @ V_chunk^T ------
// grid (64, 4); 256 threads. Z via ones-column mma. No exp here (k holds exp).
#define CT_STR 136                 // 128 + 8 bf16
#define CT_BUF (32 * CT_STR)       // 4352 bf16 per operand per stage

__global__ void __launch_bounds__(256)
ctx_kernel(const __nv_bfloat16* __restrict__ ek,
           const __nv_bfloat16* __restrict__ v,
           float* __restrict__ ctx_part,
           float* __restrict__ Z_part)
{
    __shared__ __align__(16) unsigned char smraw[4 * CT_BUF * 2];   // 34816 B
    __nv_bfloat16* sK = (__nv_bfloat16*)smraw;                      // 2 stages
    __nv_bfloat16* sV = (__nv_bfloat16*)smraw + 2 * CT_BUF;         // 2 stages
    float (*red)[1056] = (float (*)[1056])smraw;                    // aliased after loop

    const int bh = blockIdx.x, chunk = blockIdx.y;
    const int b = bh >> 2, h = bh & 3;
    const int tid = threadIdx.x, lane = tid & 31, wid = tid >> 5;

    const __nv_bfloat16* kb = ek + ((size_t)(b * MQ + h * 32)) * Nn + chunk * 1024;
    const __nv_bfloat16* vb = v  + ((size_t)(b * MQ + h * 32)) * Nn + chunk * 1024;

    const int sr = tid >> 4;             // 0..15
    const int sc = (tid & 15) * 8;       // 0..120
    auto issue = [&](int buf, int p0) {
        #pragma unroll
        for (int i = 0; i < 2; ++i) {
            int row = sr + 16 * i;
            cp_async16(sK + buf * CT_BUF + row * CT_STR + sc, kb + (size_t)row * Nn + p0 + sc);
            cp_async16(sV + buf * CT_BUF + row * CT_STR + sc, vb + (size_t)row * Nn + p0 + sc);
        }
    };

    const uint32_t sk32 = (uint32_t)__cvta_generic_to_shared(sK);
    const uint32_t sv32 = (uint32_t)__cvta_generic_to_shared(sV);
    const int kbase = wid * 16;          // warp's k-slice within each 128 tile
    const int aRow = lane & 15;
    const int aKof = (lane >> 4) * 8;
    const int eLoc = (lane & 7) + ((lane >> 4) & 1) * 8;   // 0..15
    const int pOff = ((lane >> 3) & 1) * 8;
    const uint32_t ones = (lane < 4) ? 0x3F803F80u : 0u;   // bf16 1.0 pairs, col 0

    float acc[2][4][4];                  // [mb][nb][reg]
    float zac[2][4];
    #pragma unroll
    for (int mb = 0; mb < 2; ++mb) {
        #pragma unroll
        for (int nb = 0; nb < 4; ++nb)
            #pragma unroll
            for (int i = 0; i < 4; ++i) acc[mb][nb][i] = 0.f;
        #pragma unroll
        for (int i = 0; i < 4; ++i) zac[mb][i] = 0.f;
    }

    issue(0, 0); cp_commit();
    for (int t = 0; t < 8; ++t) {
        if (t + 1 < 8) { issue((t + 1) & 1, (t + 1) * 128); cp_commit(); cp_wait<1>(); }
        else           { cp_wait<0>(); }
        __syncthreads();

        int buf = t & 1;
        uint32_t af[2][4];
        #pragma unroll
        for (int mb = 0; mb < 2; ++mb)
            ldsm_x4(af[mb], sk32 + (buf * CT_BUF + (mb * 16 + aRow) * CT_STR + kbase + aKof) * 2);
        uint32_t bv2[2][4];
        #pragma unroll
        for (int eb = 0; eb < 2; ++eb)
            ldsm_x4(bv2[eb], sv32 + (buf * CT_BUF + (eb * 16 + eLoc) * CT_STR + kbase + pOff) * 2);
        #pragma unroll
        for (int mb = 0; mb < 2; ++mb) {
            #pragma unroll
            for (int eb = 0; eb < 2; ++eb) {
                mma_bf16(acc[mb][eb * 2],     af[mb], bv2[eb][0], bv2[eb][1]);
                mma_bf16(acc[mb][eb * 2 + 1], af[mb], bv2[eb][2], bv2[eb][3]);
            }
            mma_bf16(zac[mb], af[mb], ones, ones);
        }
        __syncthreads();
    }

    // ---- cross-warp reduction (red aliases staging smem; safe post-sync) --
    const int r4 = lane >> 2;
    const int c2 = (lane & 3) * 2;
    #pragma unroll
    for (int mb = 0; mb < 2; ++mb) {
        #pragma unroll
        for (int nb = 0; nb < 4; ++nb) {
            int row0 = r4 + mb * 16, row1 = row0 + 8;
            int col = c2 + nb * 8;
            red[wid][row0 * 32 + col]     = acc[mb][nb][0];
            red[wid][row0 * 32 + col + 1] = acc[mb][nb][1];
            red[wid][row1 * 32 + col]     = acc[mb][nb][2];
            red[wid][row1 * 32 + col + 1] = acc[mb][nb][3];
        }
    }
    if ((lane & 3) == 0) {
        #pragma unroll
        for (int mb = 0; mb < 2; ++mb) {
            red[wid][1024 + r4 + mb * 16]     = zac[mb][0];
            red[wid][1024 + r4 + 8 + mb * 16] = zac[mb][2];
        }
    }
    __syncthreads();
    float* cp = ctx_part + ((size_t)bh * 4 + chunk) * 1024;
    for (int i = tid; i < 1024; i += 256) {
        float s = 0.f;
        #pragma unroll
        for (int w = 0; w < 8; ++w) s += red[w][i];
        cp[i] = s;
    }
    if (tid < 32) {
        float s = 0.f;
        #pragma unroll
        for (int w = 0; w < 8; ++w) s += red[w][1024 + tid];
        Z_part[((size_t)bh * 4 + chunk) * 32 + tid] = s;
    }
}

// ---- Wc[b][c][h*32+d] = (1/Z[b,h,d]) * sum_e wo[c][h*32+e]*ctx[b,h,d,e] ---
__global__ void wc_kernel(const float* __restrict__ wo,
                          const float* __restrict__ ctx_part,
                          const float* __restrict__ Z_part,
                          __nv_bfloat16* __restrict__ Wc)
{
    int b = blockIdx.x, h = blockIdx.y;
    int bh = b * NHEAD + h;
    int c = threadIdx.x;                 // 256
    __shared__ float sc[1024];
    __shared__ float sz[32];
    for (int i = c; i < 1024; i += 256) {
        float s = 0.f;
        #pragma unroll
        for (int ch = 0; ch < 4; ++ch)
            s += ctx_part[((size_t)bh * 4 + ch) * 1024 + i];
        sc[i] = s;
    }
    if (c < 32) {
        float s = 0.f;
        #pragma unroll
        for (int ch = 0; ch < 4; ++ch)
            s += Z_part[((size_t)bh * 4 + ch) * 32 + c];
        sz[c] = 1.f / s;
    }
    __syncthreads();
    float wrow[32];
    #pragma unroll
    for (int e = 0; e < 32; ++e) wrow[e] = wo[c * MQ + h * 32 + e];
    __nv_bfloat16* wout = Wc + (size_t)b * 32768 + (size_t)c * MQ + h * 32;
    #pragma unroll 4
    for (int d = 0; d < 32; ++d) {
        float s = 0.f;
        #pragma unroll
        for (int e = 0; e < 32; ++e) s = fmaf(wrow[e], sc[d * 32 + e], s);
        wout[d] = __float2bfloat16(s * sz[d]);
    }
}

// ---- depthwise 3x3 + GELU gate: column strips + register sliding window ---
__global__ void __launch_bounds__(256) dw_gate(const __nv_bfloat16* __restrict__ u,
                                               const float* __restrict__ dw,
                                               __nv_bfloat16* __restrict__ out)
{
    __shared__ __nv_bfloat16 sa[4096];
    __shared__ __nv_bfloat16 sg[4096];
    int hc = blockIdx.x;
    int b  = blockIdx.y;
    int tid = threadIdx.x;
    const __nv_bfloat16* ua = u + ((size_t)(b * MU + hc)) * Nn;
    const __nv_bfloat16* ug = ua + (size_t)HIDc * Nn;
    ((uint4*)sa)[tid]       = ((const uint4*)ua)[tid];
    ((uint4*)sa)[tid + 256] = ((const uint4*)ua)[tid + 256];
    ((uint4*)sg)[tid]       = ((const uint4*)ug)[tid];
    ((uint4*)sg)[tid + 256] = ((const uint4*)ug)[tid + 256];
    __syncthreads();

    float wa[9], wg[9];
    #pragma unroll
    for (int i = 0; i < 9; ++i) {
        wa[i] = dw[hc * 9 + i];
        wg[i] = dw[(HIDc + hc) * 9 + i];
    }

    const int x  = tid & 63;
    const int ys = (tid >> 6) << 4;      // 0, 16, 32, 48
    const bool xl = x > 0, xr = x < 63;

    // sliding 3x3 window: rows y-1, y, y+1 at cols x-1, x, x+1
    float a0[3], a1[3], a2[3], g0[3], g1[3], g2[3];
    if (ys == 0) {
        a0[0] = a0[1] = a0[2] = 0.f;
        g0[0] = g0[1] = g0[2] = 0.f;
    } else {
        int r = (ys - 1) * 64 + x;
        a0[0] = xl ? __bfloat162float(sa[r - 1]) : 0.f;
        a0[1] = __bfloat162float(sa[r]);
        a0[2] = xr ? __bfloat162float(sa[r + 1]) : 0.f;
        g0[0] = xl ? __bfloat162float(sg[r - 1]) : 0.f;
        g0[1] = __bfloat162float(sg[r]);
        g0[2] = xr ? __bfloat162float(sg[r + 1]) : 0.f;
    }
    {
        int r = ys * 64 + x;
        a1[0] = xl ? __bfloat162float(sa[r - 1]) : 0.f;
        a1[1] = __bfloat162float(sa[r]);
        a1[2] = xr ? __bfloat162float(sa[r + 1]) : 0.f;
        g1[0] = xl ? __bfloat162float(sg[r - 1]) : 0.f;
        g1[1] = __bfloat162float(sg[r]);
        g1[2] = xr ? __bfloat162float(sg[r + 1]) : 0.f;
    }

    __nv_bfloat16* ob = out + ((size_t)(b * HIDc + hc)) * Nn;
    #pragma unroll
    for (int i = 0; i < 16; ++i) {
        int y = ys + i;
        if (y + 1 < 64) {
            int r = (y + 1) * 64 + x;
            a2[0] = xl ? __bfloat162float(sa[r - 1]) : 0.f;
            a2[1] = __bfloat162float(sa[r]);
            a2[2] = xr ? __bfloat162float(sa[r + 1]) : 0.f;
            g2[0] = xl ? __bfloat162float(sg[r - 1]) : 0.f;
            g2[1] = __bfloat162float(sg[r]);
            g2[2] = xr ? __bfloat162float(sg[r + 1]) : 0.f;
        } else {
            a2[0] = a2[1] = a2[2] = 0.f;
            g2[0] = g2[1] = g2[2] = 0.f;
        }
        float a = wa[0]*a0[0] + wa[1]*a0[1] + wa[2]*a0[2]
                + wa[3]*a1[0] + wa[4]*a1[1] + wa[5]*a1[2]
                + wa[6]*a2[0] + wa[7]*a2[1] + wa[8]*a2[2];
        float g = wg[0]*g0[0] + wg[1]*g0[1] + wg[2]*g0[2]
                + wg[3]*g1[0] + wg[4]*g1[1] + wg[5]*g1[2]
                + wg[6]*g2[0] + wg[7]*g2[1] + wg[8]*g2[2];
        float ge = 0.5f * g * (1.f + erff(g * 0.70710678118654752f));
        ob[y * 64 + x] = __float2bfloat16(a * ge);
        #pragma unroll
        for (int j = 0; j < 3; ++j) {
            a0[j] = a1[j]; a1[j] = a2[j];
            g0[j] = g1[j]; g1[j] = g2[j];
        }
    }
}

// ---------------- host launch ----------------
extern "C" void kernel_launch(void* const* d_in, const int* in_sizes, int n_in,
                              void* d_out, int out_size)
{
    const float* x    = (const float*)d_in[0];
    const float* ln1w = (const float*)d_in[1];
    const float* ln1b = (const float*)d_in[2];
    const float* ln2w = (const float*)d_in[3];
    const float* ln2b = (const float*)d_in[4];
    const float* wq   = (const float*)d_in[5];
    const float* bq   = (const float*)d_in[6];
    const float* wk   = (const float*)d_in[7];
    const float* bk   = (const float*)d_in[8];
    const float* wv   = (const float*)d_in[9];
    const float* bv   = (const float*)d_in[10];
    const float* wo   = (const float*)d_in[11];
    const float* bo   = (const float*)d_in[12];
    const float* nqw  = (const float*)d_in[13];
    const float* nqb  = (const float*)d_in[14];
    const float* nkw  = (const float*)d_in[15];
    const float* nkb  = (const float*)d_in[16];
    const float* nvw  = (const float*)d_in[17];
    const float* nvb  = (const float*)d_in[18];
    const float* pw1  = (const float*)d_in[19];
    const float* dww  = (const float*)d_in[20];
    const float* pw2  = (const float*)d_in[21];
    float* out = (float*)d_out;

    unsigned char* A = nullptr;
    cudaGetSymbolAddress((void**)&A, g_arena);
    __nv_bfloat16* xn   = (__nv_bfloat16*)(A + BY_XN);
    __nv_bfloat16* q    = (__nv_bfloat16*)(A + BY_Q);
    __nv_bfloat16* k    = (__nv_bfloat16*)(A + BY_K);   // exp(k~)
    __nv_bfloat16* v    = (__nv_bfloat16*)(A + BY_V);
    float*         x1   = (float*)(A + BY_X1);
    __nv_bfloat16* u    = (__nv_bfloat16*)(A + BY_U);
    __nv_bfloat16* gate = (__nv_bfloat16*)(A + BY_GATE);
    float*         ctxp = (float*)(A + BY_CTX);
    float*         Zp   = (float*)(A + BY_Z);
    __nv_bfloat16* wqkv = (__nv_bfloat16*)(A + BY_WQKV);
    float*         bqkv = (float*)(A + BY_BQKV);
    __nv_bfloat16* Wc   = (__nv_bfloat16*)(A + BY_WC);
    __nv_bfloat16* pw1b = (__nv_bfloat16*)(A + BY_PW1);
    __nv_bfloat16* pw2b = (__nv_bfloat16*)(A + BY_PW2);

    conv_weights<<<1920, 256>>>(wq, wk, wv, bq, bk, bv, pw1, pw2,
                                wqkv, bqkv, pw1b, pw2b);

    dim3 ln_grid(Nn / 512, Bsz);

    // --- attention branch ---
    ln_channels<<<ln_grid, 256>>>(x, ln1w, ln1b, xn);

    // fused qkv GEMM + per-head LN (+softmax-d for q, exp for k), bf16 out
    dim3 gqkv(Nn / 128, 3, Bsz);
    gemm_bf16<true, false, 2><<<gqkv, 256>>>(
        wqkv, xn, bqkv, nullptr, q, Cc, 0,
        (size_t)MQ * Nn, (size_t)Bsz * MQ * Nn,
        nqw, nqb, nkw, nkb, nvw, nvb);

    dim3 cg(Bsz * NHEAD, 4);
    ctx_kernel<<<cg, 256>>>(k, v, ctxp, Zp);

    dim3 wcg(Bsz, NHEAD);
    wc_kernel<<<wcg, 256>>>(wo, ctxp, Zp, Wc);

    // x1 = x + Wc_b @ q + bo; xn = LN2(x1)  (fused)
    dim3 gw(Nn / 64, Bsz);
    gemm_wo_ln<<<gw, 256>>>(Wc, q, bo, x, ln2w, ln2b, x1, xn);

    // --- FFN branch ---
    dim3 g1(Nn / 128, MU / 128, Bsz);
    gemm_bf16<false, false, 1><<<g1, 256>>>(
        pw1b, xn, nullptr, nullptr, u, Cc, 0,
        (size_t)MU * Nn, (size_t)128 * Nn,
        nullptr, nullptr, nullptr, nullptr, nullptr, nullptr);

    dim3 dg(HIDc, Bsz);
    dw_gate<<<dg, 256>>>(u, dww, gate);

    dim3 g2(Nn / 128, Cc / 128, Bsz);
    gemm_bf16<false, true, 0><<<g2, 256>>>(
        pw2b, gate, nullptr, x1, out, HIDc, 0,
        (size_t)Cc * Nn, (size_t)128 * Nn,
        nullptr, nullptr, nullptr, nullptr, nullptr, nullptr);
}